// round 1
// baseline (speedup 1.0000x reference)
#include <cuda_runtime.h>

// ---------------------------------------------------------------------------
// SO8 rotation gate:
//   A = theta - theta^T  (per 8x8 block)
//   R = expm(A) via scale(2^s)+Taylor(12)+repeated squaring (global max_s)
//   y[..., n, o] = sum_e x[..., n, e] * R[n, e, o]
// ---------------------------------------------------------------------------

#define NB_MAX 4096
__device__ float g_R[NB_MAX * 64];
__device__ float g_s[NB_MAX];

// K1: per-block Taylor series. grid = nb blocks, 64 threads (one per element).
__global__ void k_taylor(const float* __restrict__ theta, int nb) {
    int n = blockIdx.x;
    int t = threadIdx.x;
    int i = t >> 3, j = t & 7;

    float a = theta[n * 64 + i * 8 + j] - theta[n * 64 + j * 8 + i];

    // Frobenius norm^2 reduction over the 64 threads (2 warps)
    float v = a * a;
    #pragma unroll
    for (int off = 16; off; off >>= 1) v += __shfl_down_sync(0xffffffffu, v, off);
    __shared__ float red[2];
    if ((t & 31) == 0) red[t >> 5] = v;
    __syncthreads();
    float norm = sqrtf(red[0] + red[1]);

    float s = fmaxf(ceilf(log2f(norm + 1e-7f)), 0.0f);
    float as = a / (exp2f(s) + 1e-7f);

    __shared__ float As[64], P[64];
    As[t] = as;
    P[t]  = as;
    float r = (i == j ? 1.0f : 0.0f) + as;  // I + A_scaled / 1!
    float fact = 1.0f;
    __syncthreads();

    #pragma unroll
    for (int it = 2; it <= 12; ++it) {
        fact *= (float)it;
        float acc = 0.0f;
        #pragma unroll
        for (int k = 0; k < 8; ++k) acc += P[i * 8 + k] * As[k * 8 + j];
        r += acc / fact;
        __syncthreads();      // all reads of P done before overwrite
        P[t] = acc;
        __syncthreads();
    }

    g_R[n * 64 + t] = r;
    if (t == 0) g_s[n] = s;
}

// K2: global max_s, then square every block max_s times (SQ_CAP = 8).
__global__ void k_square(int nb) {
    int n = blockIdx.x;
    int t = threadIdx.x;
    int i = t >> 3, j = t & 7;

    float m = 0.0f;
    for (int k = t; k < nb; k += 64) m = fmaxf(m, g_s[k]);
    #pragma unroll
    for (int off = 16; off; off >>= 1)
        m = fmaxf(m, __shfl_down_sync(0xffffffffu, m, off));
    __shared__ float red[2];
    if ((t & 31) == 0) red[t >> 5] = m;
    __syncthreads();
    float max_s = fmaxf(red[0], red[1]);

    __shared__ float Ra[64], Rb[64];
    Ra[t] = g_R[n * 64 + t];
    __syncthreads();

    float* src = Ra;
    float* dst = Rb;
    for (int k = 0; k < 8; ++k) {
        if ((float)k < max_s) {          // uniform across the block
            float acc = 0.0f;
            #pragma unroll
            for (int e = 0; e < 8; ++e) acc += src[i * 8 + e] * src[e * 8 + j];
            __syncthreads();
            dst[t] = acc;
            __syncthreads();
            float* tmp = src; src = dst; dst = tmp;
        }
    }
    g_R[n * 64 + t] = src[t];
}

// K3: bandwidth-bound apply. Thread owns one block's 8x8 R in registers,
// streams 32 rows of its 8-wide column group with float4 I/O.
__global__ __launch_bounds__(256) void k_apply(const float4* __restrict__ x,
                                               float4* __restrict__ y,
                                               int nb, long rows) {
    int n = blockIdx.x * 256 + threadIdx.x;
    if (n >= nb) return;

    float r[64];
    const float4* Rv = reinterpret_cast<const float4*>(&g_R[n * 64]);
    #pragma unroll
    for (int q = 0; q < 16; ++q) {
        float4 v = Rv[q];
        r[q * 4 + 0] = v.x; r[q * 4 + 1] = v.y;
        r[q * 4 + 2] = v.z; r[q * 4 + 3] = v.w;
    }

    long row0   = (long)blockIdx.y * 32;
    long stride = (long)nb * 2;               // row stride in float4 units
    long base   = row0 * stride + (long)n * 2;

    #pragma unroll 4
    for (int rr = 0; rr < 32; ++rr) {
        long row = row0 + rr;
        if (row >= rows) break;
        float4 a = x[base];
        float4 b = x[base + 1];
        float xv[8] = {a.x, a.y, a.z, a.w, b.x, b.y, b.z, b.w};
        float yv[8];
        #pragma unroll
        for (int o = 0; o < 8; ++o) {
            float acc = xv[0] * r[o];
            #pragma unroll
            for (int e = 1; e < 8; ++e) acc = fmaf(xv[e], r[e * 8 + o], acc);
            yv[o] = acc;
        }
        y[base]     = make_float4(yv[0], yv[1], yv[2], yv[3]);
        y[base + 1] = make_float4(yv[4], yv[5], yv[6], yv[7]);
        base += stride;
    }
}

extern "C" void kernel_launch(void* const* d_in, const int* in_sizes, int n_in,
                              void* d_out, int out_size) {
    const float* x     = (const float*)d_in[0];
    const float* theta = (const float*)d_in[1];
    float* out         = (float*)d_out;

    int  nb    = in_sizes[1] / 64;            // number of 8x8 blocks (512)
    long total = (long)in_sizes[0];
    long rows  = total / ((long)nb * 8);      // B*T (16384)

    k_taylor<<<nb, 64>>>(theta, nb);
    k_square<<<nb, 64>>>(nb);

    dim3 grid((nb + 255) / 256, (unsigned)((rows + 31) / 32));
    k_apply<<<grid, 256>>>((const float4*)x, (float4*)out, nb, rows);
}

// round 2
// speedup vs baseline: 1.3495x; 1.3495x over previous
#include <cuda_runtime.h>

// ---------------------------------------------------------------------------
// SO8 rotation gate:
//   A = theta - theta^T  (per 8x8 block)
//   R = expm(A) via scale(2^s)+Taylor(12)+repeated squaring (global max_s)
//   y[..., n, o] = sum_e x[..., n, e] * R[n, e, o]
// ---------------------------------------------------------------------------

#define NB_MAX 4096
__device__ float g_R[NB_MAX * 64];
__device__ float g_s[NB_MAX];
// permuted R for the apply kernel: column chunk c = n*2+h owns 8 float4s,
// g_Rp[(c*8 + k)*4 + c4] = R[n][e][h*4+c4] with k = (e + 4h) & 7
__device__ float g_Rp[NB_MAX * 64];

// K1: per-block Taylor series. 4 matrix-blocks per 256-thread CTA.
__global__ __launch_bounds__(256) void k_taylor(const float* __restrict__ theta, int nb) {
    __shared__ float As[4][64], P[4][64], red[4][2];
    int sub = threadIdx.x >> 6;        // which of the 4 matrix blocks
    int t   = threadIdx.x & 63;
    int i = t >> 3, j = t & 7;
    int n  = blockIdx.x * 4 + sub;
    int nc = min(n, nb - 1);           // clamp so inactive threads stay uniform

    float a = theta[nc * 64 + i * 8 + j] - theta[nc * 64 + j * 8 + i];

    // Frobenius norm^2 over the 64 threads of this sub-block (2 warps)
    float v = a * a;
    #pragma unroll
    for (int off = 16; off; off >>= 1) v += __shfl_down_sync(0xffffffffu, v, off);
    if ((threadIdx.x & 31) == 0) red[sub][(threadIdx.x >> 5) & 1] = v;
    __syncthreads();
    float norm = sqrtf(red[sub][0] + red[sub][1]);

    float s  = fmaxf(ceilf(log2f(norm + 1e-7f)), 0.0f);
    float as = a / (exp2f(s) + 1e-7f);

    As[sub][t] = as;
    P[sub][t]  = as;
    float r = (i == j ? 1.0f : 0.0f) + as;   // I + A/1!
    float fact = 1.0f;
    __syncthreads();

    // P row i lives entirely within one warp (rows 0-3 -> warp even, 4-7 -> odd),
    // and As is constant after the sync above, so warp-level sync suffices.
    #pragma unroll
    for (int it = 2; it <= 12; ++it) {
        fact *= (float)it;
        float acc = 0.0f;
        #pragma unroll
        for (int k = 0; k < 8; ++k) acc += P[sub][i * 8 + k] * As[sub][k * 8 + j];
        r += acc / fact;
        __syncwarp();
        P[sub][t] = acc;
        __syncwarp();
    }

    if (n < nb) {
        g_R[n * 64 + t] = r;
        if (t == 0) g_s[n] = s;
    }
}

// K2: global max_s, square every block max_s times, emit permuted R table.
__global__ __launch_bounds__(256) void k_square(int nb) {
    __shared__ float buf[4][2][64];
    __shared__ float redm[8];
    int sub = threadIdx.x >> 6;
    int t   = threadIdx.x & 63;
    int i = t >> 3, j = t & 7;
    int n  = blockIdx.x * 4 + sub;
    int nc = min(n, nb - 1);

    float m = 0.0f;
    for (int k = threadIdx.x; k < nb; k += 256) m = fmaxf(m, g_s[k]);
    #pragma unroll
    for (int off = 16; off; off >>= 1)
        m = fmaxf(m, __shfl_down_sync(0xffffffffu, m, off));
    if ((threadIdx.x & 31) == 0) redm[threadIdx.x >> 5] = m;
    __syncthreads();
    float max_s = redm[0];
    #pragma unroll
    for (int w = 1; w < 8; ++w) max_s = fmaxf(max_s, redm[w]);

    buf[sub][0][t] = g_R[nc * 64 + t];
    __syncthreads();

    int cur = 0;
    for (int k = 0; k < 8; ++k) {
        if ((float)k < max_s) {       // uniform across the whole CTA
            float acc = 0.0f;
            #pragma unroll
            for (int e = 0; e < 8; ++e)
                acc += buf[sub][cur][i * 8 + e] * buf[sub][cur][e * 8 + j];
            buf[sub][cur ^ 1][t] = acc;   // writes go to the other buffer: no hazard
            __syncthreads();
            cur ^= 1;
        }
    }

    if (n < nb) {
        float val = buf[sub][cur][t];     // R[n][i][j]
        int h  = j >> 2;
        int kk = (i + 4 * h) & 7;
        int c4 = j & 3;
        g_Rp[(((n * 2 + h) * 8) + kk) * 4 + c4] = val;
    }
}

// K3: bandwidth-bound apply. Thread owns a half-block (4 output columns, 32 R
// regs), loads one float4 per row (fully coalesced), gets the other 4 inputs
// from its pair lane via shfl_xor. Half-swap is pre-baked into g_Rp.
__global__ __launch_bounds__(256) void k_apply(const float4* __restrict__ x,
                                               float4* __restrict__ y,
                                               int cols, int rows, int rpc) {
    int c = blockIdx.x * 256 + threadIdx.x;   // column in float4 units
    if (c >= cols) return;

    float r[32];
    const float4* Rp = reinterpret_cast<const float4*>(g_Rp) + (long)c * 8;
    #pragma unroll
    for (int q = 0; q < 8; ++q) {
        float4 v = Rp[q];
        r[q * 4 + 0] = v.x; r[q * 4 + 1] = v.y;
        r[q * 4 + 2] = v.z; r[q * 4 + 3] = v.w;
    }

    long row0 = (long)blockIdx.y * rpc;
    int  nr   = (int)min((long)rpc, (long)rows - row0);
    long idx  = row0 * (long)cols + c;

    #pragma unroll 4
    for (int rr = 0; rr < nr; ++rr, idx += cols) {
        float4 v = x[idx];
        float z4 = __shfl_xor_sync(0xffffffffu, v.x, 1);
        float z5 = __shfl_xor_sync(0xffffffffu, v.y, 1);
        float z6 = __shfl_xor_sync(0xffffffffu, v.z, 1);
        float z7 = __shfl_xor_sync(0xffffffffu, v.w, 1);
        float4 o;
        o.x = fmaf(z7, r[28], fmaf(z6, r[24], fmaf(z5, r[20], fmaf(z4, r[16],
              fmaf(v.w, r[12], fmaf(v.z, r[8],  fmaf(v.y, r[4],  v.x * r[0])))))));
        o.y = fmaf(z7, r[29], fmaf(z6, r[25], fmaf(z5, r[21], fmaf(z4, r[17],
              fmaf(v.w, r[13], fmaf(v.z, r[9],  fmaf(v.y, r[5],  v.x * r[1])))))));
        o.z = fmaf(z7, r[30], fmaf(z6, r[26], fmaf(z5, r[22], fmaf(z4, r[18],
              fmaf(v.w, r[14], fmaf(v.z, r[10], fmaf(v.y, r[6],  v.x * r[2])))))));
        o.w = fmaf(z7, r[31], fmaf(z6, r[27], fmaf(z5, r[23], fmaf(z4, r[19],
              fmaf(v.w, r[15], fmaf(v.z, r[11], fmaf(v.y, r[7],  v.x * r[3])))))));
        y[idx] = o;
    }
}

extern "C" void kernel_launch(void* const* d_in, const int* in_sizes, int n_in,
                              void* d_out, int out_size) {
    const float* x     = (const float*)d_in[0];
    const float* theta = (const float*)d_in[1];
    float* out         = (float*)d_out;

    int  nb    = in_sizes[1] / 64;               // number of 8x8 blocks
    long total = (long)in_sizes[0];
    int  rows  = (int)(total / ((long)nb * 8));  // B*T

    k_taylor<<<(nb + 3) / 4, 256>>>(theta, nb);
    k_square<<<(nb + 3) / 4, 256>>>(nb);

    int cols = nb * 2;                           // float4 columns per row
    int rpc  = 64;                               // rows per CTA
    dim3 grid((cols + 255) / 256, (rows + rpc - 1) / rpc);
    k_apply<<<grid, 256>>>((const float4*)x, (float4*)out, cols, rows, rpc);
}